// round 13
// baseline (speedup 1.0000x reference)
#include <cuda_runtime.h>
#include <cuda_bf16.h>
#include <cuda_fp16.h>
#include <cstdint>

#define NLAYERS 4
#define HID 512
#define BATCH 32
#define SEQ 2048
#define MTOT (BATCH*SEQ)          // 65536
#define NC 128                    // scan chunks
#define TC (SEQ/NC)               // 16 steps per chunk
#define STEP 8                    // timesteps per reduction round in scan_ln
#define H2 (HID/2)                // 256 channel-pairs per row
#define H4 (HID/4)                // 128 channel-quads per row

// ---------------- GEMM tiling ----------------
#define BM 128
#define BN 128
#define BK 32
#define LDA 40                    // BK + 8 pad (row = 80B)
#define LDB 136                   // BN + 8 pad (row = 272B)
#define STAGE_EL (BM*LDA + BK*LDB)                // 9472 fp16
#define SMEM_BYTES (2*STAGE_EL*2)                 // 37888 bytes

// ---------------- scratch ----------------
__device__ __half g_ah[(size_t)MTOT * HID];       // a = sigmoid(-k)   (fp16)
__device__ __half g_gp[(size_t)MTOT * HID];       // gp = g(p)         (fp16)
__device__ __half g_Af[(size_t)MTOT * HID];       // activations / residual (fp16)
__device__ __half g_Wf[(size_t)NLAYERS * 2 * HID * HID];  // weights (fp16)
__device__ float g_cA[BATCH * NC * HID];
__device__ float g_cB[BATCH * NC * HID];
__device__ float g_hin[BATCH * NC * HID];

// ---------------- helpers ----------------
__device__ __forceinline__ uint32_t saddr(const void* p) {
    return (uint32_t)__cvta_generic_to_shared(p);
}
__device__ __forceinline__ void cpasync16(void* smem, const void* g) {
    asm volatile("cp.async.cg.shared.global [%0], [%1], 16;"
                 :: "r"(saddr(smem)), "l"(g));
}
__device__ __forceinline__ void cp_commit() {
    asm volatile("cp.async.commit_group;");
}
__device__ __forceinline__ void cp_wait0() {
    asm volatile("cp.async.wait_group 0;");
}
__device__ __forceinline__ void ldm_x4(uint32_t* r, uint32_t a) {
    asm volatile("ldmatrix.sync.aligned.m8n8.x4.shared.b16 {%0,%1,%2,%3}, [%4];"
                 : "=r"(r[0]), "=r"(r[1]), "=r"(r[2]), "=r"(r[3]) : "r"(a));
}
__device__ __forceinline__ void ldm_x2t(uint32_t* r, uint32_t a) {
    asm volatile("ldmatrix.sync.aligned.m8n8.x2.trans.shared.b16 {%0,%1}, [%2];"
                 : "=r"(r[0]), "=r"(r[1]) : "r"(a));
}
__device__ __forceinline__ void mma16816(float* c, const uint32_t* a, const uint32_t* b) {
    asm volatile(
        "mma.sync.aligned.m16n8k16.row.col.f32.f16.f16.f32 "
        "{%0,%1,%2,%3}, {%4,%5,%6,%7}, {%8,%9}, {%0,%1,%2,%3};"
        : "+f"(c[0]), "+f"(c[1]), "+f"(c[2]), "+f"(c[3])
        : "r"(a[0]), "r"(a[1]), "r"(a[2]), "r"(a[3]), "r"(b[0]), "r"(b[1]));
}
__device__ __forceinline__ float sig_neg(float v) {     // sigmoid(-v)
    return __fdividef(1.f, 1.f + __expf(v));
}
__device__ __forceinline__ float gfun(float v) {        // minGRU g()
    return (v >= 0.f) ? (v + 0.5f) : __fdividef(1.f, 1.f + __expf(-v));
}
__device__ __forceinline__ float4 half4_to_float4(uint2 v) {
    float2 lo = __half22float2(*(__half2*)&v.x);
    float2 hi = __half22float2(*(__half2*)&v.y);
    return make_float4(lo.x, lo.y, hi.x, hi.y);
}

// ============================================================================
// One-shot conversion kernels
// ============================================================================
__global__ void __launch_bounds__(256) conv_w(const float* __restrict__ Wz,
                                              const float* __restrict__ Wh) {
    size_t i = (size_t)blockIdx.x * 256 + threadIdx.x;    // over 4*512*512
    size_t l = i >> 18, r = i & ((1u << 18) - 1);
    g_Wf[((l * 2 + 0) << 18) + r] = __float2half_rn(Wz[i]);
    g_Wf[((l * 2 + 1) << 18) + r] = __float2half_rn(Wh[i]);
}

__global__ void __launch_bounds__(256) conv_x(const float* __restrict__ x) {
    size_t i = (size_t)blockIdx.x * 256 + threadIdx.x;    // over MTOT*HID/2
    float2 v = ((const float2*)x)[i];
    ((__half2*)g_Af)[i] = __floats2half2_rn(v.x, v.y);
}

// ============================================================================
// Fused dual GEMM, fp16 operands, fp32 accumulate.
// Epilogue applies the gate activation: zsel=0 stores a=sigmoid(-(k)),
// zsel=1 stores gp=g(p).  grid = (8, MTOT/128).
// ============================================================================
__global__ void __launch_bounds__(256, 2) gates_gemm(
    int layer, const float* __restrict__ bz, const float* __restrict__ bh)
{
    extern __shared__ __align__(16) char smem_raw[];
    __half* s = (__half*)smem_raw;

    const int tid  = threadIdx.x;
    const int lane = tid & 31;
    const int warp = tid >> 5;
    const int wm   = warp >> 2;
    const int wn   = warp & 3;
    const int zsel = blockIdx.x >> 2;
    const int colBase = (blockIdx.x & 3) * BN;
    const size_t rowBase = (size_t)blockIdx.y * BM;

    const __half* W_   = g_Wf + (((size_t)layer * 2 + zsel) << 18);
    const float* bias  = zsel ? bh : bz;
    __half*      Out   = zsel ? g_gp : g_ah;

    auto issue = [&](int kt, int st) {
        __half* sb = s + st * STAGE_EL;
        {   // A: 512 chunks of 16B (4 per row), 2 per thread
#pragma unroll
            for (int j = 0; j < 2; ++j) {
                int i = tid + 256 * j;
                int row = i >> 2, ch = i & 3;
                const __half* gsrc = g_Af + (rowBase + row) * HID + kt * BK + ch * 8;
                cpasync16(sb + row * LDA + ch * 8, gsrc);
            }
        }
        {   // B: 512 chunks of 16B (16 per row), 2 per thread
#pragma unroll
            for (int j = 0; j < 2; ++j) {
                int i = tid + 256 * j;
                int row = i >> 4, ch = i & 15;
                const __half* gsrc = W_ + (size_t)(kt * BK + row) * HID + colBase + ch * 8;
                cpasync16(sb + BM * LDA + row * LDB + ch * 8, gsrc);
            }
        }
        cp_commit();
    };

    float acc[4][4][4];
#pragma unroll
    for (int mt = 0; mt < 4; ++mt)
#pragma unroll
        for (int nt = 0; nt < 4; ++nt)
#pragma unroll
            for (int r = 0; r < 4; ++r) acc[mt][nt][r] = 0.f;

    auto comp = [&](int st) {
        const __half* sA = s + st * STAGE_EL;
        const __half* sB = sA + BM * LDA;
#pragma unroll
        for (int ks = 0; ks < 2; ++ks) {
            uint32_t B[4][2];
#pragma unroll
            for (int nt = 0; nt < 4; ++nt) {
                int br = ks * 16 + (lane & 15);
                int bc = wn * 32 + nt * 8;
                ldm_x2t(B[nt], saddr(sB + br * LDB + bc));
            }
#pragma unroll
            for (int mt = 0; mt < 4; ++mt) {
                uint32_t A[4];
                int ar = wm * 64 + mt * 16 + (lane & 15);
                int ac = ks * 16 + ((lane >> 4) << 3);
                ldm_x4(A, saddr(sA + ar * LDA + ac));
#pragma unroll
                for (int nt = 0; nt < 4; ++nt)
                    mma16816(acc[mt][nt], A, B[nt]);
            }
        }
    };

    issue(0, 0);
    const int KI = HID / BK;    // 16
    for (int kt = 0; kt < KI; ++kt) {
        int st = kt & 1;
        cp_wait0();
        __syncthreads();
        if (kt + 1 < KI) issue(kt + 1, st ^ 1);
        comp(st);
    }

#pragma unroll
    for (int mt = 0; mt < 4; ++mt) {
        size_t r0 = rowBase + wm * 64 + mt * 16 + (lane >> 2);
#pragma unroll
        for (int nt = 0; nt < 4; ++nt) {
            int cb = colBase + wn * 32 + nt * 8 + ((lane & 3) << 1);
            float2 bs = *(const float2*)(bias + cb);
            float v0 = acc[mt][nt][0] + bs.x, v1 = acc[mt][nt][1] + bs.y;
            float v2 = acc[mt][nt][2] + bs.x, v3 = acc[mt][nt][3] + bs.y;
            if (zsel == 0) {
                v0 = sig_neg(v0); v1 = sig_neg(v1);
                v2 = sig_neg(v2); v3 = sig_neg(v3);
            } else {
                v0 = gfun(v0); v1 = gfun(v1);
                v2 = gfun(v2); v3 = gfun(v3);
            }
            *(__half2*)(Out + r0 * HID + cb)       = __floats2half2_rn(v0, v1);
            *(__half2*)(Out + (r0 + 8) * HID + cb) = __floats2half2_rn(v2, v3);
        }
    }
}

// ============================================================================
// Scan summary pass: chunk (P, S); pure FMA (activations precomputed).
// grid = BATCH*NC = 4096 blocks x 128 threads, 4 channels/thread, TC=16 steps.
// ============================================================================
__global__ void __launch_bounds__(128) scan_summary() {
    int b     = blockIdx.x >> 7;                  // NC = 128
    int chunk = blockIdx.x & (NC - 1);
    int c4    = threadIdx.x;                      // quad index 0..127
    size_t base = ((size_t)(b * SEQ + chunk * TC)) * H4 + c4;

    const uint2* a4g = (const uint2*)g_ah;
    const uint2* g4g = (const uint2*)g_gp;

    float S[4] = {0.f, 0.f, 0.f, 0.f};
    float P[4] = {1.f, 1.f, 1.f, 1.f};
#pragma unroll
    for (int t = 0; t < TC; ++t) {
        size_t o = base + (size_t)t * H4;
        float4 a = half4_to_float4(__ldcs(a4g + o));
        float4 g = half4_to_float4(__ldcs(g4g + o));
        S[0] = fmaf(a.x, S[0] - g.x, g.x);  P[0] *= a.x;
        S[1] = fmaf(a.y, S[1] - g.y, g.y);  P[1] *= a.y;
        S[2] = fmaf(a.z, S[2] - g.z, g.z);  P[2] *= a.z;
        S[3] = fmaf(a.w, S[3] - g.w, g.w);  P[3] *= a.w;
    }
    ((float4*)g_cA)[(b * NC + chunk) * H4 + c4] = make_float4(P[0], P[1], P[2], P[3]);
    ((float4*)g_cB)[(b * NC + chunk) * H4 + c4] = make_float4(S[0], S[1], S[2], S[3]);
}

// ============================================================================
// Chain chunk summaries; emit per-chunk h_in and final hiddens.
// ============================================================================
__global__ void __launch_bounds__(256) scanB(const float* __restrict__ h0l,
                                             float* __restrict__ hid_out) {
    int idx = blockIdx.x * 256 + threadIdx.x;   // 16384
    int b = idx >> 9, c = idx & 511;
    float x0 = h0l[b * HID + c];
    float h = (x0 >= 0.f) ? (x0 + 0.5f)
                          : __fdividef(1.f, 1.f + __expf(-x0));
#pragma unroll 16
    for (int j = 0; j < NC; ++j) {
        g_hin[(b * NC + j) * HID + c] = h;
        h = fmaf(g_cA[(b * NC + j) * HID + c], h, g_cB[(b * NC + j) * HID + c]);
    }
    hid_out[b * HID + c] = h;
}

// ============================================================================
// Fused scan + LayerNorm + residual (pure-FMA recurrence).
// One block per (b, chunk): 128 threads x 4 channels; TC=16 in 2 STEP-rounds.
// Residual source: fp32 x (layer 0) or fp16 g_Af in place (layers 1..3).
// Output: layers 0-2 write only fp16 g_Af; layer 3 writes only fp32 d_out.
// ============================================================================
__global__ void __launch_bounds__(128, 3) scan_ln(const float* __restrict__ residf,
                                                  const float* __restrict__ gamma,
                                                  const float* __restrict__ beta,
                                                  float* __restrict__ outp,
                                                  int resid_is_fp16,
                                                  int write_out,
                                                  int write_split) {
    __shared__ float red[4][16];      // [warp][8 x s, 8 x s2]
    __shared__ float bcast[2][STEP];  // [mu | rstd][step]
    int b = blockIdx.x >> 7, chunk = blockIdx.x & (NC - 1);
    int c4 = threadIdx.x, lane = c4 & 31, warp = c4 >> 5;

    float4 h   = ((const float4*)g_hin)[(b * NC + chunk) * H4 + c4];
    float4 gm  = __ldg((const float4*)gamma + c4);
    float4 bt  = __ldg((const float4*)beta + c4);
    size_t base4 = ((size_t)b * SEQ + chunk * TC) * H4 + c4;   // quad index

    const uint2*  a4g    = (const uint2*)g_ah;
    const uint2*  g4g    = (const uint2*)g_gp;
    const uint2*  residh = (const uint2*)g_Af;   // device-side symbol address
    const float4* r4g    = (const float4*)residf;
    float4*       o4g    = (float4*)outp;
    uint2*        af4g   = (uint2*)g_Af;

    uint2  ac[STEP], gc[STEP];
    float4 rc[STEP];
#pragma unroll
    for (int j = 0; j < STEP; ++j) {              // prologue loads (round 0)
        size_t o = base4 + (size_t)j * H4;
        ac[j] = __ldcs(a4g + o);
        gc[j] = __ldcs(g4g + o);
        rc[j] = resid_is_fp16 ? half4_to_float4(__ldcs(residh + o))
                              : __ldcs(r4g + o);
    }

#pragma unroll
    for (int t0 = 0; t0 < TC; t0 += STEP) {
        float4 h8[STEP];
        float s8[STEP], q8[STEP];
#pragma unroll
        for (int j = 0; j < STEP; ++j) {          // 8-step h chain (4 ch)
            float4 av = half4_to_float4(ac[j]);
            float4 gv = half4_to_float4(gc[j]);
            h.x = fmaf(av.x, h.x - gv.x, gv.x);
            h.y = fmaf(av.y, h.y - gv.y, gv.y);
            h.z = fmaf(av.z, h.z - gv.z, gv.z);
            h.w = fmaf(av.w, h.w - gv.w, gv.w);
            h8[j] = h;
            s8[j] = (h.x + h.y) + (h.z + h.w);
            q8[j] = (h.x * h.x + h.y * h.y) + (h.z * h.z + h.w * h.w);
        }
        float4 r8[STEP];
#pragma unroll
        for (int j = 0; j < STEP; ++j) r8[j] = rc[j];

        // prefetch next round while the reduction runs
        if (t0 + STEP < TC) {
#pragma unroll
            for (int j = 0; j < STEP; ++j) {
                size_t o = base4 + (size_t)(t0 + STEP + j) * H4;
                ac[j] = __ldcs(a4g + o);
                gc[j] = __ldcs(g4g + o);
                rc[j] = resid_is_fp16 ? half4_to_float4(__ldcs(residh + o))
                                      : __ldcs(r4g + o);
            }
        }

        // warp butterfly: 16 independent reductions, full ILP
#pragma unroll
        for (int off = 16; off; off >>= 1) {
#pragma unroll
            for (int j = 0; j < STEP; ++j) {
                s8[j] += __shfl_xor_sync(0xffffffffu, s8[j], off);
                q8[j] += __shfl_xor_sync(0xffffffffu, q8[j], off);
            }
        }
        if (lane == 0) {
#pragma unroll
            for (int j = 0; j < STEP; ++j) {
                red[warp][j]        = s8[j];
                red[warp][j + STEP] = q8[j];
            }
        }
        __syncthreads();
        if (warp == 0) {
            float v = 0.f;
            if (lane < 16) {
#pragma unroll
                for (int w = 0; w < 4; ++w) v += red[w][lane];
            }
            float vq = __shfl_down_sync(0xffffffffu, v, STEP);
            if (lane < STEP) {
                float mu  = v * (1.f / HID);
                float var = fmaf(vq, 1.f / HID, -mu * mu);
                bcast[0][lane] = mu;
                bcast[1][lane] = rsqrtf(var + 1e-5f);
            }
        }
        __syncthreads();
#pragma unroll
        for (int j = 0; j < STEP; ++j) {
            size_t o = base4 + (size_t)(t0 + j) * H4;
            float mu = bcast[0][j], rstd = bcast[1][j];
            float4 ov;
            ov.x = (h8[j].x - mu) * rstd * gm.x + bt.x + r8[j].x;
            ov.y = (h8[j].y - mu) * rstd * gm.y + bt.y + r8[j].y;
            ov.z = (h8[j].z - mu) * rstd * gm.z + bt.z + r8[j].z;
            ov.w = (h8[j].w - mu) * rstd * gm.w + bt.w + r8[j].w;
            if (write_out)
                __stcs(o4g + o, ov);
            if (write_split) {
                uint2 pk;
                *(__half2*)&pk.x = __floats2half2_rn(ov.x, ov.y);
                *(__half2*)&pk.y = __floats2half2_rn(ov.z, ov.w);
                __stcs(af4g + o, pk);
            }
        }
    }
}

// ============================================================================
extern "C" void kernel_launch(void* const* d_in, const int* in_sizes, int n_in,
                              void* d_out, int out_size)
{
    const float* x     = (const float*)d_in[0];
    const float* h0    = (const float*)d_in[1];
    const float* Wz    = (const float*)d_in[2];
    const float* bz    = (const float*)d_in[3];
    const float* Wh    = (const float*)d_in[4];
    const float* bh    = (const float*)d_in[5];
    const float* gamma = (const float*)d_in[6];
    const float* beta  = (const float*)d_in[7];

    float* out_cur = (float*)d_out;                       // (B, T, H)
    float* out_hid = out_cur + (size_t)MTOT * HID;        // (L, B, H)

    conv_w<<<(NLAYERS * HID * HID) / 256, 256>>>(Wz, Wh);
    conv_x<<<(MTOT * HID / 2) / 256, 256>>>(x);

    for (int i = 0; i < NLAYERS; ++i) {
        gates_gemm<<<dim3(8, MTOT / BM), 256, SMEM_BYTES>>>(
            i, bz + i * HID, bh + i * HID);
        scan_summary<<<BATCH * NC, 128>>>();
        scanB<<<64, 256>>>(h0 + (size_t)i * BATCH * HID,
                           out_hid + (size_t)i * BATCH * HID);
        int last = (i == NLAYERS - 1);
        scan_ln<<<BATCH * NC, 128>>>(
            x,                                  // fp32 resid (layer 0 only)
            gamma + i * HID, beta + i * HID,
            out_cur,
            /*resid_is_fp16=*/(i > 0) ? 1 : 0,
            /*write_out=*/last,
            /*write_split=*/last ? 0 : 1);
    }
}